// round 4
// baseline (speedup 1.0000x reference)
#include <cuda_runtime.h>
#include <math.h>
#include <stdint.h>

#define NB 16
#define NTE 64
#define NTD 32
#define NE 256
#define NH 512
#define NG 2048
#define NV 90000
#define NEGV (-1e9f)

typedef unsigned long long u64;

// ---------------- device scratch (static, no allocation) ----------------
__device__ float g_qemb[NB*NTE*NE];   // [b][t][e]
__device__ float g_remb[NB*NTD*NE];   // [b][t][e]
__device__ float g_h[2][NB*NH];       // ping-pong LSTM h
__device__ float g_c[2][NB*NH];       // ping-pong LSTM c
__device__ float g_attn[NB*NH];       // decoder attention state
__device__ float g_encout[NB*NTE*NH]; // [b][te][h]
__device__ float g_keys[NB*NTE*NH];   // [b][te][k]
__device__ float g_pq[NB*NH];
__device__ float g_ctx[NB*NH];
__device__ float g_A[NB*NTD*NH];      // attn2 rows: row = b*NTD+t
__device__ float g_AcT[NH*NB*NTD];    // compacted+transposed A: [k][m]
__device__ int   g_outrow[NB*NTD];
__device__ int   g_nrows;
__device__ float g_W2e[768*NG];       // permuted W_enc: [k][jblk][jl*4+q]
__device__ float g_W2d[1280*NG];      // permuted W_dec
__device__ unsigned g_barE;
__device__ unsigned g_barD;

__device__ __forceinline__ float sigf(float x) { return 1.0f / (1.0f + expf(-x)); }

__device__ __forceinline__ u64 packdup(float v) {
    u64 r;
    asm("mov.b64 %0, {%1, %1};" : "=l"(r) : "r"(__float_as_uint(v)));
    return r;
}
__device__ __forceinline__ void fma2(u64& d, u64 a, u64 b) {
    asm("fma.rn.f32x2 %0, %1, %2, %0;" : "+l"(d) : "l"(a), "l"(b));
}
__device__ __forceinline__ void unpack2(u64 v, float& lo, float& hi) {
    unsigned l, h;
    asm("mov.b64 {%0, %1}, %2;" : "=r"(l), "=r"(h) : "l"(v));
    lo = __uint_as_float(l); hi = __uint_as_float(h);
}

// grid-wide barrier: release-arrive + acquire-spin (all CTAs co-resident by construction)
__device__ __forceinline__ void gbar(unsigned* ctr, unsigned target) {
    __syncthreads();
    if (threadIdx.x == 0) {
        __threadfence();
        atomicAdd(ctr, 1u);
        unsigned v;
        do {
            asm volatile("ld.global.acquire.gpu.u32 %0, [%1];" : "=r"(v) : "l"(ctr) : "memory");
        } while (v < target);
    }
    __syncthreads();
}

// ---------------- prep ----------------
__global__ void prep_kernel(const int* __restrict__ enc_in, const int* __restrict__ dec_in,
                            const int* __restrict__ dlen, const float* __restrict__ emb)
{
    int idx = blockIdx.x * blockDim.x + threadIdx.x;
    int stride = gridDim.x * blockDim.x;
    for (int i = idx; i < NB*NTE*NE; i += stride) {
        int e = i & (NE - 1); int bt = i >> 8;
        g_qemb[i] = emb[(size_t)enc_in[bt] * NE + e];
    }
    for (int i = idx; i < NB*NTD*NE; i += stride) {
        int e = i & (NE - 1); int bt = i >> 8;
        g_remb[i] = emb[(size_t)dec_in[bt] * NE + e];
    }
    for (int i = idx; i < NB*NH; i += stride) {
        g_h[0][i] = 0.f; g_c[0][i] = 0.f; g_attn[i] = 0.f;
    }
    if (idx == 0) {
        g_barE = 0u; g_barD = 0u;
        int n = 0;
        for (int b = 0; b < NB; b++) {
            int L = dlen[b]; if (L > NTD) L = NTD; if (L < 0) L = 0;
            for (int t2 = 0; t2 < L; t2++) g_outrow[n++] = b * NTD + t2;
        }
        g_nrows = n;
    }
}

// ---------------- permute LSTM weights: W2[k][blk*16 + jl*4 + q] = W[k][q*512+blk*4+jl] ----------------
__global__ void permW_kernel(const float* __restrict__ We, const float* __restrict__ Wd)
{
    int idx = blockIdx.x * blockDim.x + threadIdx.x;
    int stride = gridDim.x * blockDim.x;
    for (int i = idx; i < 768*NG; i += stride) {
        int k = i >> 11, g2 = i & (NG - 1);
        int blk = g2 >> 4, x = g2 & 15, jl = x >> 2, q = x & 3;
        g_W2e[i] = We[(size_t)k*NG + q*NH + (blk << 2) + jl];
    }
    for (int i = idx; i < 1280*NG; i += stride) {
        int k = i >> 11, g2 = i & (NG - 1);
        int blk = g2 >> 4, x = g2 & 15, jl = x >> 2, q = x & 3;
        g_W2d[i] = Wd[(size_t)k*NG + q*NH + (blk << 2) + jl];
    }
}

__global__ void zero_kernel(float4* __restrict__ out, int n4)
{
    int idx = blockIdx.x * blockDim.x + threadIdx.x;
    int stride = gridDim.x * blockDim.x;
    float4 z = make_float4(0.f, 0.f, 0.f, 0.f);
    for (int i = idx; i < n4; i += stride) out[i] = z;
}

// ---------------- persistent encoder: 64 steps, weights in registers ----------------
// 128 CTAs x 256 thr; CTA c owns gate block (4 j x 4 gates = 16 cols); thread (gl, s).
__global__ void __launch_bounds__(256, 1)
enc_mega(const float* __restrict__ bias, const int* __restrict__ elen)
{
    extern __shared__ float sm[];
    float* xs = sm;               // [768][16]
    float* zp = sm + 768*16;      // [16s][16gl][16b]
    float* zz = zp + 4096;        // [16gl][16b]

    int tid = threadIdx.x;
    int c = blockIdx.x;
    int gl = tid & 15, s = tid >> 4;
    int k0 = s * 48;

    float wreg[48];
    {
        const float* Wp = g_W2e + (c << 4) + gl;
        #pragma unroll
        for (int kk = 0; kk < 48; kk++) wreg[kk] = Wp[(size_t)(k0 + kk) * NG];
    }
    // bias for reduce stage (thread role g2 = tid>>4, b = tid&15)
    int g2r = tid >> 4;
    float bv = bias[(g2r & 3)*NH + (c << 2) + (g2r >> 2)];

    unsigned tgt = 0;
    for (int t = 0; t < NTE; t++) {
        const float* h_in  = g_h[t & 1];
        const float* c_in  = g_c[t & 1];
        float* h_out = g_h[(t + 1) & 1];
        float* c_out = g_c[(t + 1) & 1];

        // stage x = [emb | h] transposed to [k][b]
        #pragma unroll
        for (int b = 0; b < 16; b++)
            for (int k = tid; k < 768; k += 256) {
                float v = (k < NE) ? g_qemb[(b*NTE + t)*NE + k] : h_in[b*NH + (k - NE)];
                xs[k*16 + b] = v;
            }
        __syncthreads();

        u64 acc[8];
        #pragma unroll
        for (int p = 0; p < 8; p++) acc[p] = 0ULL;
        #pragma unroll
        for (int kk = 0; kk < 48; kk++) {
            u64 w2 = packdup(wreg[kk]);
            const u64* xk = (const u64*)(xs + (k0 + kk)*16);
            #pragma unroll
            for (int p = 0; p < 8; p++) fma2(acc[p], xk[p], w2);
        }
        #pragma unroll
        for (int p = 0; p < 8; p++) {
            float lo, hi; unpack2(acc[p], lo, hi);
            zp[tid*16 + 2*p]   = lo;
            zp[tid*16 + 2*p+1] = hi;
        }
        __syncthreads();

        {   // reduce 16 k-splits + bias
            int g2 = tid >> 4, b = tid & 15;
            float sum = 0.f;
            #pragma unroll
            for (int ss = 0; ss < 16; ss++) sum += zp[(ss*16 + g2)*16 + b];
            zz[g2*16 + b] = sum + bv;
        }
        __syncthreads();

        if (tid < 64) {
            int jl = tid >> 4, b = tid & 15;
            int jg = (c << 2) + jl;
            float iv = zz[(jl*4 + 0)*16 + b];
            float jv = zz[(jl*4 + 1)*16 + b];
            float fv = zz[(jl*4 + 2)*16 + b];
            float ov = zz[(jl*4 + 3)*16 + b];
            float cold = c_in[b*NH + jg];
            float c2 = cold * sigf(fv + 1.f) + sigf(iv) * tanhf(jv);
            float h2 = tanhf(c2) * sigf(ov);
            bool valid = t < elen[b];
            float hold = xs[(NE + jg)*16 + b];
            h_out[b*NH + jg] = valid ? h2 : hold;
            c_out[b*NH + jg] = valid ? c2 : cold;
            g_encout[((size_t)b*NTE + t)*NH + jg] = valid ? h2 : 0.f;
        }
        tgt += 128;
        gbar(&g_barE, tgt);
    }
}

// ---------------- keys = enc_out @ W_mem ----------------
__global__ void keys_kernel(const float* __restrict__ Wm)
{
    extern __shared__ float sm[];
    const int KX = NH, KP = NH + 4;
    float* xs = sm;
    float* ws = sm + 16*KP;
    int tid = threadIdx.x;
    int cn = blockIdx.x;
    int cr = blockIdx.y;

    for (int i = tid; i < 16*KX; i += 256) {
        int rl = i >> 9, k = i & 511;
        xs[rl*KP + k] = g_encout[(cr*16 + rl)*NH + k];
    }
    for (int i = tid; i < 16*KX; i += 256) {
        int k = i >> 4, nl = i & 15;
        ws[nl*KP + k] = Wm[k*NH + cn*16 + nl];
    }
    __syncthreads();

    int nl = tid & 15, rl = tid >> 4;
    float a0 = 0.f, a1 = 0.f, a2 = 0.f, a3 = 0.f;
    const float* xp = xs + rl*KP;
    const float* wp = ws + nl*KP;
    #pragma unroll 8
    for (int k = 0; k < KX; k += 4) {
        float4 a = *(const float4*)(xp + k);
        float4 w = *(const float4*)(wp + k);
        a0 = fmaf(a.x, w.x, a0);
        a1 = fmaf(a.y, w.y, a1);
        a2 = fmaf(a.z, w.z, a2);
        a3 = fmaf(a.w, w.w, a3);
    }
    g_keys[(cr*16 + rl)*NH + cn*16 + nl] = (a0 + a1) + (a2 + a3);
}

// ---------------- persistent decoder: 32 steps x 4 phases ----------------
// 128 CTAs x 256 thr. Phase1: LSTM (CTA = 16 gate cols, weights in regs).
// Phase2: pq (CTA = 4 n-cols, all b). Phase3: scores+softmax+ctx (CTA = b, c<16).
// Phase4: attn2 (CTA = 4 n-cols, all b).
__global__ void __launch_bounds__(256, 1)
dec_mega(const float* __restrict__ bias, const float* __restrict__ Wq,
         const float* __restrict__ vatt, const float* __restrict__ Wa,
         const int* __restrict__ elen)
{
    extern __shared__ float sm[];
    float* xs = sm;               // phase1: [1280][16]; phase2: h2s[16][520]; phase4: cat[16][1032]
    float* zp = sm + 1280*16;     // phase1: partials [16][16][16]; phase2/4: partials [256][4]
    float* zz = zp + 4096;        // phase1: [16][16]
    float* pqv = sm;              // phase3 (c<16): pq row
    float* vsv = sm + 512;
    float* scv = sm + 1024;       // 64 scores

    int tid = threadIdx.x;
    int c = blockIdx.x;
    int gl = tid & 15, s = tid >> 4;
    int k0 = s * 80;

    float wreg[80];
    {
        const float* Wp = g_W2d + (c << 4) + gl;
        #pragma unroll
        for (int kk = 0; kk < 80; kk++) wreg[kk] = Wp[(size_t)(k0 + kk) * NG];
    }
    int g2r = tid >> 4;
    float bv = bias[(g2r & 3)*NH + (c << 2) + (g2r >> 2)];

    int n0 = c * 4;               // n-slice for phases 2 & 4
    int bq = tid & 15, ks = tid >> 4;

    unsigned tgt = 0;
    for (int t = 0; t < NTD; t++) {
        const float* h_in  = g_h[t & 1];
        const float* c_in  = g_c[t & 1];
        float* h_out = g_h[(t + 1) & 1];
        float* c_out = g_c[(t + 1) & 1];

        // ===== phase 1: LSTM =====
        #pragma unroll
        for (int b = 0; b < 16; b++)
            for (int k = tid; k < 1280; k += 256) {
                float v;
                if (k < NE)           v = g_remb[(b*NTD + t)*NE + k];
                else if (k < NE + NH) v = g_attn[b*NH + (k - NE)];
                else                  v = h_in[b*NH + (k - NE - NH)];
                xs[k*16 + b] = v;
            }
        __syncthreads();

        {
            u64 acc[8];
            #pragma unroll
            for (int p = 0; p < 8; p++) acc[p] = 0ULL;
            #pragma unroll
            for (int kk = 0; kk < 80; kk++) {
                u64 w2 = packdup(wreg[kk]);
                const u64* xk = (const u64*)(xs + (k0 + kk)*16);
                #pragma unroll
                for (int p = 0; p < 8; p++) fma2(acc[p], xk[p], w2);
            }
            #pragma unroll
            for (int p = 0; p < 8; p++) {
                float lo, hi; unpack2(acc[p], lo, hi);
                zp[tid*16 + 2*p]   = lo;
                zp[tid*16 + 2*p+1] = hi;
            }
        }
        __syncthreads();
        {
            int g2 = tid >> 4, b = tid & 15;
            float sum = 0.f;
            #pragma unroll
            for (int ss = 0; ss < 16; ss++) sum += zp[(ss*16 + g2)*16 + b];
            zz[g2*16 + b] = sum + bv;
        }
        __syncthreads();
        if (tid < 64) {
            int jl = tid >> 4, b = tid & 15;
            int jg = (c << 2) + jl;
            float iv = zz[(jl*4 + 0)*16 + b];
            float jv = zz[(jl*4 + 1)*16 + b];
            float fv = zz[(jl*4 + 2)*16 + b];
            float ov = zz[(jl*4 + 3)*16 + b];
            float cold = c_in[b*NH + jg];
            float c2 = cold * sigf(fv + 1.f) + sigf(iv) * tanhf(jv);
            float h2 = tanhf(c2) * sigf(ov);
            h_out[b*NH + jg] = h2;
            c_out[b*NH + jg] = c2;
        }
        tgt += 128; gbar(&g_barD, tgt);

        // ===== phase 2: pq = h2 @ Wq (this CTA: 4 n-cols, all b) =====
        #pragma unroll
        for (int b = 0; b < 16; b++)
            for (int k = tid; k < 512; k += 256)
                xs[b*520 + k] = h_out[b*NH + k];
        __syncthreads();
        {
            const float* wqp = Wq + (size_t)(ks*32)*NH + n0;
            const float* hrow = xs + bq*520 + ks*32;
            float a0 = 0.f, a1 = 0.f, a2 = 0.f, a3 = 0.f;
            #pragma unroll
            for (int kk = 0; kk < 32; kk++) {
                float4 w = *(const float4*)(wqp + (size_t)kk*NH);
                float x = hrow[kk];
                a0 = fmaf(x, w.x, a0);
                a1 = fmaf(x, w.y, a1);
                a2 = fmaf(x, w.z, a2);
                a3 = fmaf(x, w.w, a3);
            }
            zp[tid*4 + 0] = a0; zp[tid*4 + 1] = a1;
            zp[tid*4 + 2] = a2; zp[tid*4 + 3] = a3;
        }
        __syncthreads();
        if (tid < 64) {
            int bb = tid >> 2, j = tid & 3;
            float sv = 0.f;
            #pragma unroll
            for (int ss = 0; ss < 16; ss++) sv += zp[(ss*16 + bb)*4 + j];
            g_pq[bb*NH + n0 + j] = sv;
        }
        tgt += 128; gbar(&g_barD, tgt);

        // ===== phase 3: scores + softmax + ctx (CTAs 0..15, b = c) =====
        if (c < 16) {
            int b = c;
            for (int i = tid; i < NH; i += 256) { pqv[i] = g_pq[b*NH + i]; vsv[i] = vatt[i]; }
            __syncthreads();
            int w = tid >> 5, l = tid & 31;
            int len = elen[b];
            for (int te = w; te < NTE; te += 8) {
                const float* kp = g_keys + ((size_t)b*NTE + te)*NH;
                float p = 0.f;
                for (int h = l; h < NH; h += 32)
                    p += vsv[h] * tanhf(kp[h] + pqv[h]);
                #pragma unroll
                for (int off = 16; off > 0; off >>= 1) p += __shfl_xor_sync(0xffffffffu, p, off);
                if (l == 0) scv[te] = (te < len) ? p : NEGV;
            }
            __syncthreads();
            if (tid < 32) {
                float a = scv[tid], b2 = scv[tid + 32];
                float m = fmaxf(a, b2);
                #pragma unroll
                for (int off = 16; off > 0; off >>= 1) m = fmaxf(m, __shfl_xor_sync(0xffffffffu, m, off));
                float e1 = expf(a - m), e2 = expf(b2 - m);
                float ssum = e1 + e2;
                #pragma unroll
                for (int off = 16; off > 0; off >>= 1) ssum += __shfl_xor_sync(0xffffffffu, ssum, off);
                float inv = 1.f / ssum;
                scv[tid] = e1 * inv; scv[tid + 32] = e2 * inv;
            }
            __syncthreads();
            for (int h = tid; h < NH; h += 256) {
                float acc = 0.f;
                const float* ep = g_encout + (size_t)b*NTE*NH + h;
                #pragma unroll 8
                for (int te = 0; te < NTE; te++)
                    acc = fmaf(scv[te], ep[(size_t)te*NH], acc);
                g_ctx[b*NH + h] = acc;
            }
        }
        tgt += 128; gbar(&g_barD, tgt);

        // ===== phase 4: attn2 = [h2|ctx] @ Wa (this CTA: 4 n-cols, all b) =====
        #pragma unroll
        for (int b = 0; b < 16; b++)
            for (int k = tid; k < 1024; k += 256) {
                float v = (k < NH) ? h_out[b*NH + k] : g_ctx[b*NH + (k - NH)];
                xs[b*1032 + k] = v;
            }
        __syncthreads();
        {
            const float* wap = Wa + (size_t)(ks*64)*NH + n0;
            const float* crow = xs + bq*1032 + ks*64;
            float a0 = 0.f, a1 = 0.f, a2 = 0.f, a3 = 0.f;
            #pragma unroll
            for (int kk = 0; kk < 64; kk++) {
                float4 w = *(const float4*)(wap + (size_t)kk*NH);
                float x = crow[kk];
                a0 = fmaf(x, w.x, a0);
                a1 = fmaf(x, w.y, a1);
                a2 = fmaf(x, w.z, a2);
                a3 = fmaf(x, w.w, a3);
            }
            zp[tid*4 + 0] = a0; zp[tid*4 + 1] = a1;
            zp[tid*4 + 2] = a2; zp[tid*4 + 3] = a3;
        }
        __syncthreads();
        if (tid < 64) {
            int bb = tid >> 2, j = tid & 3;
            float sv = 0.f;
            #pragma unroll
            for (int ss = 0; ss < 16; ss++) sv += zp[(ss*16 + bb)*4 + j];
            g_attn[bb*NH + n0 + j] = sv;
            g_A[((size_t)bb*NTD + t)*NH + n0 + j] = sv;
        }
        tgt += 128; gbar(&g_barD, tgt);
    }
}

// ---------------- compact valid rows + transpose A -> [k][m] ----------------
__global__ void compactT_kernel()
{
    int idx = blockIdx.x * blockDim.x + threadIdx.x;
    int stride = gridDim.x * blockDim.x;
    int nr = g_nrows;
    for (int i = idx; i < NH*NB*NTD; i += stride) {
        int k = i >> 9, m = i & 511;
        g_AcT[i] = (m < nr) ? g_A[g_outrow[m]*NH + k] : 0.f;
    }
}

// ---------------- projection: [nrows,512] @ [512,90000], f32x2 ----------------
__global__ void proj_kernel(const float* __restrict__ Wp, float* __restrict__ out)
{
    __shared__ float2 As2[16*64];
    __shared__ float  Bs[16*128];
    int m0 = blockIdx.x * 64;
    int n0 = blockIdx.y * 128;
    int nr = g_nrows;
    if (m0 >= nr) return;

    int tid = threadIdx.x;
    int tx = tid & 31, ty = tid >> 5;
    u64 acc2[8][2];
    #pragma unroll
    for (int i = 0; i < 8; i++) { acc2[i][0] = 0ULL; acc2[i][1] = 0ULL; }

    for (int kt = 0; kt < NH; kt += 16) {
        for (int i = tid; i < 1024; i += 256) {
            int k = i >> 6, m = i & 63;
            float v = g_AcT[(kt + k)*(NB*NTD) + m0 + m];
            As2[i] = make_float2(v, v);
        }
        for (int i = tid; i < 2048; i += 256) {
            int k = i >> 7, n = i & 127;
            int nn = n0 + n;
            Bs[i] = (nn < NV) ? Wp[(size_t)(kt + k)*NV + nn] : 0.f;
        }
        __syncthreads();
        #pragma unroll
        for (int k = 0; k < 16; k++) {
            u64 b01 = *(const u64*)&Bs[k*128 + tx*4];
            u64 b23 = *(const u64*)&Bs[k*128 + tx*4 + 2];
            const u64* ap = (const u64*)&As2[k*64 + ty*8];
            #pragma unroll
            for (int i = 0; i < 8; i++) {
                u64 a = ap[i];
                fma2(acc2[i][0], a, b01);
                fma2(acc2[i][1], a, b23);
            }
        }
        __syncthreads();
    }

    #pragma unroll
    for (int i = 0; i < 8; i++) {
        int m = m0 + ty*8 + i;
        if (m < nr) {
            int row = g_outrow[m];
            int nn = n0 + tx*4;
            float v0, v1, v2, v3;
            unpack2(acc2[i][0], v0, v1);
            unpack2(acc2[i][1], v2, v3);
            float* op = out + (size_t)row*NV + nn;
            if (nn + 3 < NV) {
                *(float4*)op = make_float4(v0, v1, v2, v3);
            } else {
                float vv[4] = {v0, v1, v2, v3};
                #pragma unroll
                for (int j = 0; j < 4; j++) if (nn + j < NV) op[j] = vv[j];
            }
        }
    }
}

// ---------------- launch ----------------
extern "C" void kernel_launch(void* const* d_in, const int* in_sizes, int n_in,
                              void* d_out, int out_size)
{
    const int*   enc_in  = (const int*)d_in[0];
    const int*   dec_in  = (const int*)d_in[1];
    const int*   elen    = (const int*)d_in[2];
    const int*   dlen    = (const int*)d_in[3];
    const float* emb     = (const float*)d_in[4];
    const float* W_enc   = (const float*)d_in[5];
    const float* b_enc   = (const float*)d_in[6];
    const float* W_dec   = (const float*)d_in[7];
    const float* b_dec   = (const float*)d_in[8];
    const float* W_mem   = (const float*)d_in[9];
    const float* W_query = (const float*)d_in[10];
    const float* v_att   = (const float*)d_in[11];
    const float* W_attn  = (const float*)d_in[12];
    const float* W_proj  = (const float*)d_in[13];
    float* out = (float*)d_out;

    const int smemE = (768*16 + 4096 + 256) * 4;    //  66560 B
    const int smemD = (1280*16 + 4096 + 256) * 4;   //  99328 B
    const int smemK = (2*16*(NH + 4)) * 4;          //  66048 B

    cudaFuncSetAttribute(enc_mega,    cudaFuncAttributeMaxDynamicSharedMemorySize, smemE);
    cudaFuncSetAttribute(dec_mega,    cudaFuncAttributeMaxDynamicSharedMemorySize, smemD);
    cudaFuncSetAttribute(keys_kernel, cudaFuncAttributeMaxDynamicSharedMemorySize, smemK);

    prep_kernel<<<256, 256>>>(enc_in, dec_in, dlen, emb);
    permW_kernel<<<512, 256>>>(W_enc, W_dec);
    zero_kernel<<<1024, 256>>>((float4*)out, NB*NTD*NV/4);

    enc_mega<<<128, 256, smemE>>>(b_enc, elen);
    keys_kernel<<<dim3(32, 64), 256, smemK>>>(W_mem);
    dec_mega<<<128, 256, smemD>>>(b_dec, W_query, v_att, W_attn, elen);

    compactT_kernel<<<256, 256>>>();
    proj_kernel<<<dim3(8, 704), 256>>>(W_proj, out);
}

// round 6
// speedup vs baseline: 1.0404x; 1.0404x over previous
#include <cuda_runtime.h>
#include <cuda_bf16.h>
#include <math.h>
#include <stdint.h>

#define NB 16
#define NTE 64
#define NTD 32
#define NE 256
#define NH 512
#define NG 2048
#define NV 90000
#define NVP 90112
#define NEGV (-1e9f)

typedef unsigned long long u64;

// ---------------- device scratch (static, no allocation) ----------------
__device__ float g_qemb[NB*NTE*NE];
__device__ float g_remb[NB*NTD*NE];
__device__ float g_h[2][NB*NH];
__device__ float g_c[2][NB*NH];
__device__ float g_attn[NB*NH];
__device__ float g_encout[NB*NTE*NH];
__device__ float g_keys[NB*NTE*NH];
__device__ float g_pq[NB*NH];
__device__ float g_ctx[NB*NH];
__device__ float g_A[NB*NTD*NH];
__device__ int   g_outrow[NB*NTD];
__device__ int   g_nrows;
__device__ float g_W2e[768*NG];
__device__ float g_W2d[1280*NG];
__device__ unsigned g_barE;
__device__ unsigned g_barD;
// bf16 split operands for tensor-core projection
__device__ __nv_bfloat16 g_Wphi[(size_t)NVP*NH];   // [v][k]
__device__ __nv_bfloat16 g_Wplo[(size_t)NVP*NH];
__device__ __nv_bfloat16 g_Ahi[512*NH];            // [m][k], zero-padded m>=nrows
__device__ __nv_bfloat16 g_Alo[512*NH];

__device__ __forceinline__ float sigf(float x) { return 1.0f / (1.0f + expf(-x)); }

__device__ __forceinline__ u64 packdup(float v) {
    u64 r;
    asm("mov.b64 %0, {%1, %1};" : "=l"(r) : "r"(__float_as_uint(v)));
    return r;
}
__device__ __forceinline__ void fma2(u64& d, u64 a, u64 b) {
    asm("fma.rn.f32x2 %0, %1, %2, %0;" : "+l"(d) : "l"(a), "l"(b));
}
__device__ __forceinline__ void unpack2(u64 v, float& lo, float& hi) {
    unsigned l, h;
    asm("mov.b64 {%0, %1}, %2;" : "=r"(l), "=r"(h) : "l"(v));
    lo = __uint_as_float(l); hi = __uint_as_float(h);
}

__device__ __forceinline__ uint32_t smem_u32(const void* p) {
    uint32_t a;
    asm("{ .reg .u64 t; cvta.to.shared.u64 t, %1; cvt.u32.u64 %0, t; }" : "=r"(a) : "l"(p));
    return a;
}

// grid barrier with nanosleep backoff (avoids L2 poll storm)
__device__ __forceinline__ void gbar(unsigned* ctr, unsigned target) {
    __syncthreads();
    if (threadIdx.x == 0) {
        __threadfence();
        atomicAdd(ctr, 1u);
        unsigned v;
        for (;;) {
            asm volatile("ld.global.acquire.gpu.u32 %0, [%1];" : "=r"(v) : "l"(ctr) : "memory");
            if (v >= target) break;
            __nanosleep(64);
        }
    }
    __syncthreads();
}

// ---------------- prep ----------------
__global__ void prep_kernel(const int* __restrict__ enc_in, const int* __restrict__ dec_in,
                            const int* __restrict__ dlen, const float* __restrict__ emb)
{
    int idx = blockIdx.x * blockDim.x + threadIdx.x;
    int stride = gridDim.x * blockDim.x;
    for (int i = idx; i < NB*NTE*NE; i += stride) {
        int e = i & (NE - 1); int bt = i >> 8;
        g_qemb[i] = emb[(size_t)enc_in[bt] * NE + e];
    }
    for (int i = idx; i < NB*NTD*NE; i += stride) {
        int e = i & (NE - 1); int bt = i >> 8;
        g_remb[i] = emb[(size_t)dec_in[bt] * NE + e];
    }
    for (int i = idx; i < NB*NH; i += stride) {
        g_h[0][i] = 0.f; g_c[0][i] = 0.f; g_attn[i] = 0.f;
    }
    if (idx == 0) {
        g_barE = 0u; g_barD = 0u;
        int n = 0;
        for (int b = 0; b < NB; b++) {
            int L = dlen[b]; if (L > NTD) L = NTD; if (L < 0) L = 0;
            for (int t2 = 0; t2 < L; t2++) g_outrow[n++] = b * NTD + t2;
        }
        g_nrows = n;
    }
}

// ---------------- permute LSTM weights ----------------
__global__ void permW_kernel(const float* __restrict__ We, const float* __restrict__ Wd)
{
    int idx = blockIdx.x * blockDim.x + threadIdx.x;
    int stride = gridDim.x * blockDim.x;
    for (int i = idx; i < 768*NG; i += stride) {
        int k = i >> 11, g2 = i & (NG - 1);
        int blk = g2 >> 4, x = g2 & 15, jl = x >> 2, q = x & 3;
        g_W2e[i] = We[(size_t)k*NG + q*NH + (blk << 2) + jl];
    }
    for (int i = idx; i < 1280*NG; i += stride) {
        int k = i >> 11, g2 = i & (NG - 1);
        int blk = g2 >> 4, x = g2 & 15, jl = x >> 2, q = x & 3;
        g_W2d[i] = Wd[(size_t)k*NG + q*NH + (blk << 2) + jl];
    }
}

__global__ void zero_kernel(float4* __restrict__ out, int n4)
{
    int idx = blockIdx.x * blockDim.x + threadIdx.x;
    int stride = gridDim.x * blockDim.x;
    float4 z = make_float4(0.f, 0.f, 0.f, 0.f);
    for (int i = idx; i < n4; i += stride) out[i] = z;
}

// ---------------- W_proj -> transposed bf16 hi/lo: Wt[v][k] ----------------
__global__ void wconv_kernel(const float* __restrict__ Wp)
{
    __shared__ float tile[64][65];
    int v0 = blockIdx.x * 64, k0 = blockIdx.y * 64;
    int tid = threadIdx.x;
    for (int i = tid; i < 4096; i += 256) {
        int kk = i >> 6, vv = i & 63;
        int v = v0 + vv;
        tile[kk][vv] = (v < NV) ? Wp[(size_t)(k0 + kk)*NV + v] : 0.f;
    }
    __syncthreads();
    for (int i = tid; i < 4096; i += 256) {
        int vv = i >> 6, kk = i & 63;
        float x = tile[kk][vv];
        __nv_bfloat16 hi = __float2bfloat16(x);
        float r = x - __bfloat162float(hi);
        size_t o = (size_t)(v0 + vv)*NH + k0 + kk;
        g_Wphi[o] = hi;
        g_Wplo[o] = __float2bfloat16(r);
    }
}

// ---------------- persistent encoder (weights in smem) ----------------
__global__ void __launch_bounds__(256, 1)
enc_mega(const float* __restrict__ bias, const int* __restrict__ elen)
{
    extern __shared__ float sm[];
    float* xs = sm;                 // [768][16]
    float* zp = sm + 12288;         // [16][16][16]
    float* zz = zp + 4096;          // [16][16]
    float* ws = zz + 256;           // [768][16]

    int tid = threadIdx.x;
    int c = blockIdx.x;
    int gl = tid & 15, s = tid >> 4;
    int k0 = s * 48;

    for (int i = tid; i < 768*16; i += 256)
        ws[i] = g_W2e[(size_t)(i >> 4)*NG + (c << 4) + (i & 15)];
    int g2r = tid >> 4;
    float bv = bias[(g2r & 3)*NH + (c << 2) + (g2r >> 2)];
    __syncthreads();

    unsigned tgt = 0;
    for (int t = 0; t < NTE; t++) {
        const float* h_in  = g_h[t & 1];
        const float* c_in  = g_c[t & 1];
        float* h_out = g_h[(t + 1) & 1];
        float* c_out = g_c[(t + 1) & 1];

        #pragma unroll
        for (int b = 0; b < 16; b++)
            for (int k = tid; k < 768; k += 256) {
                float v = (k < NE) ? g_qemb[(b*NTE + t)*NE + k] : h_in[b*NH + (k - NE)];
                xs[k*16 + b] = v;
            }
        __syncthreads();

        u64 acc[8];
        #pragma unroll
        for (int p = 0; p < 8; p++) acc[p] = 0ULL;
        #pragma unroll 4
        for (int kk = 0; kk < 48; kk++) {
            int k = k0 + kk;
            u64 w2 = packdup(ws[k*16 + gl]);
            const u64* xk = (const u64*)(xs + k*16);
            #pragma unroll
            for (int p = 0; p < 8; p++) fma2(acc[p], xk[p], w2);
        }
        #pragma unroll
        for (int p = 0; p < 8; p++) {
            float lo, hi; unpack2(acc[p], lo, hi);
            zp[tid*16 + 2*p]   = lo;
            zp[tid*16 + 2*p+1] = hi;
        }
        __syncthreads();

        {
            int g2 = tid >> 4, b = tid & 15;
            float sum = 0.f;
            #pragma unroll
            for (int ss = 0; ss < 16; ss++) sum += zp[(ss*16 + g2)*16 + b];
            zz[g2*16 + b] = sum + bv;
        }
        __syncthreads();

        if (tid < 64) {
            int jl = tid >> 4, b = tid & 15;
            int jg = (c << 2) + jl;
            float iv = zz[(jl*4 + 0)*16 + b];
            float jv = zz[(jl*4 + 1)*16 + b];
            float fv = zz[(jl*4 + 2)*16 + b];
            float ov = zz[(jl*4 + 3)*16 + b];
            float cold = c_in[b*NH + jg];
            float c2 = cold * sigf(fv + 1.f) + sigf(iv) * tanhf(jv);
            float h2 = tanhf(c2) * sigf(ov);
            bool valid = t < elen[b];
            float hold = xs[(NE + jg)*16 + b];
            h_out[b*NH + jg] = valid ? h2 : hold;
            c_out[b*NH + jg] = valid ? c2 : cold;
            g_encout[((size_t)b*NTE + t)*NH + jg] = valid ? h2 : 0.f;
        }
        tgt += 128;
        gbar(&g_barE, tgt);
    }
}

// ---------------- keys = enc_out @ W_mem ----------------
__global__ void keys_kernel(const float* __restrict__ Wm)
{
    extern __shared__ float sm[];
    const int KX = NH, KP = NH + 4;
    float* xs = sm;
    float* ws = sm + 16*KP;
    int tid = threadIdx.x;
    int cn = blockIdx.x;
    int cr = blockIdx.y;

    for (int i = tid; i < 16*KX; i += 256) {
        int rl = i >> 9, k = i & 511;
        xs[rl*KP + k] = g_encout[(cr*16 + rl)*NH + k];
    }
    for (int i = tid; i < 16*KX; i += 256) {
        int k = i >> 4, nl = i & 15;
        ws[nl*KP + k] = Wm[k*NH + cn*16 + nl];
    }
    __syncthreads();

    int nl = tid & 15, rl = tid >> 4;
    float a0 = 0.f, a1 = 0.f, a2 = 0.f, a3 = 0.f;
    const float* xp = xs + rl*KP;
    const float* wp = ws + nl*KP;
    #pragma unroll 8
    for (int k = 0; k < KX; k += 4) {
        float4 a = *(const float4*)(xp + k);
        float4 w = *(const float4*)(wp + k);
        a0 = fmaf(a.x, w.x, a0);
        a1 = fmaf(a.y, w.y, a1);
        a2 = fmaf(a.z, w.z, a2);
        a3 = fmaf(a.w, w.w, a3);
    }
    g_keys[(cr*16 + rl)*NH + cn*16 + nl] = (a0 + a1) + (a2 + a3);
}

// ---------------- persistent decoder (weights in smem) ----------------
__global__ void __launch_bounds__(256, 1)
dec_mega(const float* __restrict__ bias, const float* __restrict__ Wq,
         const float* __restrict__ vatt, const float* __restrict__ Wa,
         const int* __restrict__ elen)
{
    extern __shared__ float sm[];
    float* xs  = sm;                 // [1280][16] / phase2 h2s[16][520] / phase4 cat[16][1032]
    float* zp  = sm + 20480;
    float* zz  = zp + 4096;
    float* ws  = zz + 256;           // [1280][16]
    float* wqs = ws + 20480;         // [512][4]
    float* was = wqs + 2048;         // [1024][4]
    float* pqv = sm;
    float* vsv = sm + 512;
    float* scv = sm + 1024;

    int tid = threadIdx.x;
    int c = blockIdx.x;
    int gl = tid & 15, s = tid >> 4;
    int k0 = s * 80;
    int n0 = c * 4;
    int bq = tid & 15, ks = tid >> 4;

    for (int i = tid; i < 1280*16; i += 256)
        ws[i] = g_W2d[(size_t)(i >> 4)*NG + (c << 4) + (i & 15)];
    for (int i = tid; i < 512*4; i += 256)
        wqs[i] = Wq[(size_t)(i >> 2)*NH + n0 + (i & 3)];
    for (int i = tid; i < 1024*4; i += 256)
        was[i] = Wa[(size_t)(i >> 2)*NH + n0 + (i & 3)];
    int g2r = tid >> 4;
    float bv = bias[(g2r & 3)*NH + (c << 2) + (g2r >> 2)];
    __syncthreads();

    unsigned tgt = 0;
    for (int t = 0; t < NTD; t++) {
        const float* h_in  = g_h[t & 1];
        const float* c_in  = g_c[t & 1];
        float* h_out = g_h[(t + 1) & 1];
        float* c_out = g_c[(t + 1) & 1];

        // ===== phase 1: LSTM =====
        #pragma unroll
        for (int b = 0; b < 16; b++)
            for (int k = tid; k < 1280; k += 256) {
                float v;
                if (k < NE)           v = g_remb[(b*NTD + t)*NE + k];
                else if (k < NE + NH) v = g_attn[b*NH + (k - NE)];
                else                  v = h_in[b*NH + (k - NE - NH)];
                xs[k*16 + b] = v;
            }
        __syncthreads();
        {
            u64 acc[8];
            #pragma unroll
            for (int p = 0; p < 8; p++) acc[p] = 0ULL;
            #pragma unroll 4
            for (int kk = 0; kk < 80; kk++) {
                int k = k0 + kk;
                u64 w2 = packdup(ws[k*16 + gl]);
                const u64* xk = (const u64*)(xs + k*16);
                #pragma unroll
                for (int p = 0; p < 8; p++) fma2(acc[p], xk[p], w2);
            }
            #pragma unroll
            for (int p = 0; p < 8; p++) {
                float lo, hi; unpack2(acc[p], lo, hi);
                zp[tid*16 + 2*p]   = lo;
                zp[tid*16 + 2*p+1] = hi;
            }
        }
        __syncthreads();
        {
            int g2 = tid >> 4, b = tid & 15;
            float sum = 0.f;
            #pragma unroll
            for (int ss = 0; ss < 16; ss++) sum += zp[(ss*16 + g2)*16 + b];
            zz[g2*16 + b] = sum + bv;
        }
        __syncthreads();
        if (tid < 64) {
            int jl = tid >> 4, b = tid & 15;
            int jg = (c << 2) + jl;
            float iv = zz[(jl*4 + 0)*16 + b];
            float jv = zz[(jl*4 + 1)*16 + b];
            float fv = zz[(jl*4 + 2)*16 + b];
            float ov = zz[(jl*4 + 3)*16 + b];
            float cold = c_in[b*NH + jg];
            float c2 = cold * sigf(fv + 1.f) + sigf(iv) * tanhf(jv);
            float h2 = tanhf(c2) * sigf(ov);
            h_out[b*NH + jg] = h2;
            c_out[b*NH + jg] = c2;
        }
        tgt += 128; gbar(&g_barD, tgt);

        // ===== phase 2: pq = h2 @ Wq (4 n-cols per CTA) =====
        #pragma unroll
        for (int b = 0; b < 16; b++)
            for (int k = tid; k < 512; k += 256)
                xs[b*520 + k] = h_out[b*NH + k];
        __syncthreads();
        {
            const float4* wq4 = (const float4*)wqs;
            const float* hrow = xs + bq*520 + ks*32;
            float a0 = 0.f, a1 = 0.f, a2 = 0.f, a3 = 0.f;
            #pragma unroll
            for (int kk = 0; kk < 32; kk++) {
                float4 w = wq4[ks*32 + kk];
                float x = hrow[kk];
                a0 = fmaf(x, w.x, a0);
                a1 = fmaf(x, w.y, a1);
                a2 = fmaf(x, w.z, a2);
                a3 = fmaf(x, w.w, a3);
            }
            zp[tid*4 + 0] = a0; zp[tid*4 + 1] = a1;
            zp[tid*4 + 2] = a2; zp[tid*4 + 3] = a3;
        }
        __syncthreads();
        if (tid < 64) {
            int bb = tid >> 2, j = tid & 3;
            float sv = 0.f;
            #pragma unroll
            for (int ss = 0; ss < 16; ss++) sv += zp[(ss*16 + bb)*4 + j];
            g_pq[bb*NH + n0 + j] = sv;
        }
        tgt += 128; gbar(&g_barD, tgt);

        // ===== phase 3: scores + softmax + ctx (CTAs 0..15) =====
        if (c < 16) {
            int b = c;
            for (int i = tid; i < NH; i += 256) { pqv[i] = g_pq[b*NH + i]; vsv[i] = vatt[i]; }
            __syncthreads();
            int w = tid >> 5, l = tid & 31;
            int len = elen[b];
            for (int te = w; te < NTE; te += 8) {
                const float* kp = g_keys + ((size_t)b*NTE + te)*NH;
                float p = 0.f;
                for (int h = l; h < NH; h += 32)
                    p += vsv[h] * tanhf(kp[h] + pqv[h]);
                #pragma unroll
                for (int off = 16; off > 0; off >>= 1) p += __shfl_xor_sync(0xffffffffu, p, off);
                if (l == 0) scv[te] = (te < len) ? p : NEGV;
            }
            __syncthreads();
            if (tid < 32) {
                float a = scv[tid], b2 = scv[tid + 32];
                float m = fmaxf(a, b2);
                #pragma unroll
                for (int off = 16; off > 0; off >>= 1) m = fmaxf(m, __shfl_xor_sync(0xffffffffu, m, off));
                float e1 = expf(a - m), e2 = expf(b2 - m);
                float ssum = e1 + e2;
                #pragma unroll
                for (int off = 16; off > 0; off >>= 1) ssum += __shfl_xor_sync(0xffffffffu, ssum, off);
                float inv = 1.f / ssum;
                scv[tid] = e1 * inv; scv[tid + 32] = e2 * inv;
            }
            __syncthreads();
            for (int h = tid; h < NH; h += 256) {
                float acc = 0.f;
                const float* ep = g_encout + (size_t)b*NTE*NH + h;
                #pragma unroll 8
                for (int te = 0; te < NTE; te++)
                    acc = fmaf(scv[te], ep[(size_t)te*NH], acc);
                g_ctx[b*NH + h] = acc;
            }
        }
        tgt += 128; gbar(&g_barD, tgt);

        // ===== phase 4: attn2 = [h2|ctx] @ Wa (4 n-cols per CTA) =====
        #pragma unroll
        for (int b = 0; b < 16; b++)
            for (int k = tid; k < 1024; k += 256) {
                float v = (k < NH) ? h_out[b*NH + k] : g_ctx[b*NH + (k - NH)];
                xs[b*1032 + k] = v;
            }
        __syncthreads();
        {
            const float4* wa4 = (const float4*)was;
            const float* crow = xs + bq*1032 + ks*64;
            float a0 = 0.f, a1 = 0.f, a2 = 0.f, a3 = 0.f;
            #pragma unroll
            for (int kk = 0; kk < 64; kk++) {
                float4 w = wa4[ks*64 + kk];
                float x = crow[kk];
                a0 = fmaf(x, w.x, a0);
                a1 = fmaf(x, w.y, a1);
                a2 = fmaf(x, w.z, a2);
                a3 = fmaf(x, w.w, a3);
            }
            zp[tid*4 + 0] = a0; zp[tid*4 + 1] = a1;
            zp[tid*4 + 2] = a2; zp[tid*4 + 3] = a3;
        }
        __syncthreads();
        if (tid < 64) {
            int bb = tid >> 2, j = tid & 3;
            float sv = 0.f;
            #pragma unroll
            for (int ss = 0; ss < 16; ss++) sv += zp[(ss*16 + bb)*4 + j];
            g_attn[bb*NH + n0 + j] = sv;
            g_A[((size_t)bb*NTD + t)*NH + n0 + j] = sv;
        }
        tgt += 128; gbar(&g_barD, tgt);
    }
}

// ---------------- compact + split A rows into bf16 hi/lo ----------------
__global__ void asplit_kernel()
{
    int idx = blockIdx.x * blockDim.x + threadIdx.x;
    int stride = gridDim.x * blockDim.x;
    int nr = g_nrows;
    for (int i = idx; i < 512*NH; i += stride) {
        int m = i >> 9, k = i & 511;
        float x = (m < nr) ? g_A[g_outrow[m]*NH + k] : 0.f;
        __nv_bfloat16 hi = __float2bfloat16(x);
        g_Ahi[i] = hi;
        g_Alo[i] = __float2bfloat16(x - __bfloat162float(hi));
    }
}

// ---------------- HMMA projection: D = Ahi*Whi + Ahi*Wlo + Alo*Whi ----------------
// CTA tile 128m x 128n, K=512 in 8 chunks of 64. 8 warps = 2m x 4n, warp tile 64x32.
// mma.sync.m16n8k16 bf16 (base sm_103-compatible, no tcgen05).
#define PR_LDA 72   // 64 bf16 + 8 pad (16B) per row
#define PROJ_SMEM (4*128*PR_LDA*2)

__device__ __forceinline__ void ldmA(uint32_t* a, uint32_t addr) {
    asm volatile("ldmatrix.sync.aligned.m8n8.x4.shared.b16 {%0,%1,%2,%3}, [%4];"
                 : "=r"(a[0]), "=r"(a[1]), "=r"(a[2]), "=r"(a[3]) : "r"(addr));
}
__device__ __forceinline__ void ldmB(uint32_t* b, uint32_t addr) {
    asm volatile("ldmatrix.sync.aligned.m8n8.x2.shared.b16 {%0,%1}, [%2];"
                 : "=r"(b[0]), "=r"(b[1]) : "r"(addr));
}
__device__ __forceinline__ void mma16816(float* c, const uint32_t* a, const uint32_t* b) {
    asm volatile("mma.sync.aligned.m16n8k16.row.col.f32.bf16.bf16.f32 "
                 "{%0,%1,%2,%3}, {%4,%5,%6,%7}, {%8,%9}, {%0,%1,%2,%3};"
                 : "+f"(c[0]), "+f"(c[1]), "+f"(c[2]), "+f"(c[3])
                 : "r"(a[0]), "r"(a[1]), "r"(a[2]), "r"(a[3]), "r"(b[0]), "r"(b[1]));
}

__global__ void __launch_bounds__(256, 1)
proj_hmma(float* __restrict__ out)
{
    extern __shared__ __nv_bfloat16 smb[];
    __nv_bfloat16* sAhi = smb;                    // [128][72]
    __nv_bfloat16* sAlo = smb + 128*PR_LDA;
    __nv_bfloat16* sBhi = smb + 2*128*PR_LDA;
    __nv_bfloat16* sBlo = smb + 3*128*PR_LDA;

    int m0 = blockIdx.x * 128;
    int n0 = blockIdx.y * 128;
    int nr = g_nrows;
    if (m0 >= nr) return;

    int tid = threadIdx.x;
    int wid = tid >> 5, lane = tid & 31;
    int m0w = (wid >> 2) * 64;     // 2 warp rows
    int n0w = (wid & 3) * 32;      // 4 warp cols

    uint32_t sb = smem_u32(smb);
    uint32_t aAhi = sb, aAlo = sb + 128*PR_LDA*2, aBhi = sb + 2*128*PR_LDA*2, aBlo = sb + 3*128*PR_LDA*2;

    float c[4][4][4];
    #pragma unroll
    for (int i = 0; i < 4; i++)
        #pragma unroll
        for (int j = 0; j < 4; j++)
            #pragma unroll
            for (int q = 0; q < 4; q++) c[i][j][q] = 0.f;

    for (int ch = 0; ch < 8; ch++) {
        int k0 = ch * 64;
        // cooperative loads: 128 rows x 64 bf16 per matrix (uint4 = 8 bf16)
        for (int i = tid; i < 1024; i += 256) {
            int m = i >> 3, kb = i & 7;
            size_t go = (size_t)(m0 + m)*NH + k0 + kb*8;
            int so = m*PR_LDA + kb*8;
            *(uint4*)&sAhi[so] = *(const uint4*)&g_Ahi[go];
            *(uint4*)&sAlo[so] = *(const uint4*)&g_Alo[go];
        }
        for (int i = tid; i < 1024; i += 256) {
            int n = i >> 3, kb = i & 7;
            size_t go = (size_t)(n0 + n)*NH + k0 + kb*8;
            int so = n*PR_LDA + kb*8;
            *(uint4*)&sBhi[so] = *(const uint4*)&g_Wphi[go];
            *(uint4*)&sBlo[so] = *(const uint4*)&g_Wplo[go];
        }
        __syncthreads();

        #pragma unroll
        for (int ks = 0; ks < 4; ks++) {
            int kp = ks * 16;
            uint32_t ahi[4][4], alo[4][4], bhi[4][2], blo[4][2];
            #pragma unroll
            for (int mt = 0; mt < 4; mt++) {
                uint32_t off = ((m0w + mt*16 + (lane & 15)) * PR_LDA + kp + ((lane >> 4) << 3)) * 2;
                ldmA(ahi[mt], aAhi + off);
                ldmA(alo[mt], aAlo + off);
            }
            #pragma unroll
            for (int nt = 0; nt < 4; nt++) {
                uint32_t off = ((n0w + nt*8 + (lane & 7)) * PR_LDA + kp + (((lane >> 3) & 1) << 3)) * 2;
                ldmB(bhi[nt], aBhi + off);
                ldmB(blo[nt], aBlo + off);
            }
            #pragma unroll
            for (int mt = 0; mt < 4; mt++)
                #pragma unroll
                for (int nt = 0; nt < 4; nt++) {
                    mma16816(c[mt][nt], ahi[mt], bhi[nt]);
                    mma16816(c[mt][nt], ahi[mt], blo[nt]);
                    mma16816(c[mt][nt], alo[mt], bhi[nt]);
                }
        }
        __syncthreads();
    }

    // epilogue: write C frags directly (float2 per row-pair element)
    int rg = lane >> 2, cg = (lane & 3) * 2;
    #pragma unroll
    for (int mt = 0; mt < 4; mt++) {
        #pragma unroll
        for (int half = 0; half < 2; half++) {
            int mloc = m0w + mt*16 + rg + half*8;
            int m = m0 + mloc;
            if (m < nr) {
                int orow = g_outrow[m];
                float* obase = out + (size_t)orow*NV;
                #pragma unroll
                for (int nt = 0; nt < 4; nt++) {
                    int nn = n0 + n0w + nt*8 + cg;
                    float v0 = c[mt][nt][half*2 + 0];
                    float v1 = c[mt][nt][half*2 + 1];
                    if (nn + 1 < NV) {
                        *(float2*)(obase + nn) = make_float2(v0, v1);
                    } else if (nn < NV) {
                        obase[nn] = v0;
                    }
                }
            }
        }
    }
}

// ---------------- launch ----------------
extern "C" void kernel_launch(void* const* d_in, const int* in_sizes, int n_in,
                              void* d_out, int out_size)
{
    const int*   enc_in  = (const int*)d_in[0];
    const int*   dec_in  = (const int*)d_in[1];
    const int*   elen    = (const int*)d_in[2];
    const int*   dlen    = (const int*)d_in[3];
    const float* emb     = (const float*)d_in[4];
    const float* W_enc   = (const float*)d_in[5];
    const float* b_enc   = (const float*)d_in[6];
    const float* W_dec   = (const float*)d_in[7];
    const float* b_dec   = (const float*)d_in[8];
    const float* W_mem   = (const float*)d_in[9];
    const float* W_query = (const float*)d_in[10];
    const float* v_att   = (const float*)d_in[11];
    const float* W_attn  = (const float*)d_in[12];
    const float* W_proj  = (const float*)d_in[13];
    float* out = (float*)d_out;

    const int smemE = (12288 + 4096 + 256 + 12288) * 4;                  // 115,712 B
    const int smemD = (20480 + 4096 + 256 + 20480 + 2048 + 4096) * 4;   // 205,824 B
    const int smemK = (2*16*(NH + 4)) * 4;                               //  66,048 B

    cudaFuncSetAttribute(enc_mega,    cudaFuncAttributeMaxDynamicSharedMemorySize, smemE);
    cudaFuncSetAttribute(dec_mega,    cudaFuncAttributeMaxDynamicSharedMemorySize, smemD);
    cudaFuncSetAttribute(keys_kernel, cudaFuncAttributeMaxDynamicSharedMemorySize, smemK);
    cudaFuncSetAttribute(proj_hmma,   cudaFuncAttributeMaxDynamicSharedMemorySize, PROJ_SMEM);

    prep_kernel<<<256, 256>>>(enc_in, dec_in, dlen, emb);
    permW_kernel<<<512, 256>>>(W_enc, W_dec);
    zero_kernel<<<1024, 256>>>((float4*)out, NB*NTD*NV/4);
    wconv_kernel<<<dim3(NVP/64, NH/64), 256>>>(W_proj);

    enc_mega<<<128, 256, smemE>>>(b_enc, elen);
    keys_kernel<<<dim3(32, 64), 256, smemK>>>(W_mem);
    dec_mega<<<128, 256, smemD>>>(b_dec, W_query, v_att, W_attn, elen);

    asplit_kernel<<<256, 256>>>();
    proj_hmma<<<dim3(4, 704), 256, PROJ_SMEM>>>(out);
}

// round 7
// speedup vs baseline: 1.1168x; 1.0734x over previous
#include <cuda_runtime.h>
#include <cuda_bf16.h>
#include <math.h>
#include <stdint.h>

#define NB 16
#define NTE 64
#define NTD 32
#define NE 256
#define NH 512
#define NG 2048
#define NV 90000
#define NVP 90112
#define NEGV (-1e9f)
#define PX 18   // smem pitch (floats) for [k][b] tiles: 2-way max bank conflict

typedef unsigned long long u64;

// ---------------- device scratch (static, no allocation) ----------------
__device__ float g_qemb[NB*NTE*NE];
__device__ float g_remb[NB*NTD*NE];
__device__ float g_h[2][NB*NH];
__device__ float g_c[2][NB*NH];
__device__ float g_attn[NB*NH];
__device__ float g_encout[NB*NTE*NH];
__device__ float g_keys[NB*NTE*NH];
__device__ float g_pq[NB*NH];
__device__ float g_ctx[NB*NH];
__device__ int   g_outrow[NB*NTD];
__device__ int   g_rowpos[NB*NTD];
__device__ int   g_nrows;
__device__ float g_W2e[768*NG];
__device__ float g_W2d[1280*NG];
__device__ unsigned g_barE;
__device__ unsigned g_barD;
__device__ __nv_bfloat16 g_Wphi[(size_t)NVP*NH];   // [v][k]
__device__ __nv_bfloat16 g_Wplo[(size_t)NVP*NH];
__device__ __nv_bfloat16 g_Ahi[512*NH];            // [m][k], zero-padded
__device__ __nv_bfloat16 g_Alo[512*NH];

__device__ __forceinline__ float sigf(float x) { return 1.0f / (1.0f + expf(-x)); }

__device__ __forceinline__ u64 packdup(float v) {
    u64 r;
    asm("mov.b64 %0, {%1, %1};" : "=l"(r) : "r"(__float_as_uint(v)));
    return r;
}
__device__ __forceinline__ void fma2(u64& d, u64 a, u64 b) {
    asm("fma.rn.f32x2 %0, %1, %2, %0;" : "+l"(d) : "l"(a), "l"(b));
}
__device__ __forceinline__ void unpack2(u64 v, float& lo, float& hi) {
    unsigned l, h;
    asm("mov.b64 {%0, %1}, %2;" : "=r"(l), "=r"(h) : "l"(v));
    lo = __uint_as_float(l); hi = __uint_as_float(h);
}
__device__ __forceinline__ uint32_t smem_u32(const void* p) {
    uint32_t a;
    asm("{ .reg .u64 t; cvta.to.shared.u64 t, %1; cvt.u32.u64 %0, t; }" : "=r"(a) : "l"(p));
    return a;
}

// grid barrier: release arrival + pure acquire spin (all CTAs co-resident)
__device__ __forceinline__ void gbar(unsigned* ctr, unsigned target) {
    __syncthreads();
    if (threadIdx.x == 0) {
        __threadfence();
        atomicAdd(ctr, 1u);
        unsigned v;
        do {
            asm volatile("ld.global.acquire.gpu.u32 %0, [%1];" : "=r"(v) : "l"(ctr) : "memory");
        } while (v < target);
    }
    __syncthreads();
}

// ---------------- prep ----------------
__global__ void prep_kernel(const int* __restrict__ enc_in, const int* __restrict__ dec_in,
                            const int* __restrict__ dlen, const float* __restrict__ emb)
{
    int idx = blockIdx.x * blockDim.x + threadIdx.x;
    int stride = gridDim.x * blockDim.x;
    for (int i = idx; i < NB*NTE*NE; i += stride) {
        int e = i & (NE - 1); int bt = i >> 8;
        g_qemb[i] = emb[(size_t)enc_in[bt] * NE + e];
    }
    for (int i = idx; i < NB*NTD*NE; i += stride) {
        int e = i & (NE - 1); int bt = i >> 8;
        g_remb[i] = emb[(size_t)dec_in[bt] * NE + e];
    }
    for (int i = idx; i < NB*NH; i += stride) {
        g_h[0][i] = 0.f; g_c[0][i] = 0.f; g_attn[i] = 0.f;
    }
    __nv_bfloat16 z = __float2bfloat16(0.f);
    for (int i = idx; i < 512*NH; i += stride) { g_Ahi[i] = z; g_Alo[i] = z; }
    if (idx == 0) {
        g_barE = 0u; g_barD = 0u;
        int n = 0;
        for (int b = 0; b < NB; b++) {
            int L = dlen[b]; if (L > NTD) L = NTD; if (L < 0) L = 0;
            for (int t2 = 0; t2 < NTD; t2++) {
                if (t2 < L) { g_outrow[n] = b*NTD + t2; g_rowpos[b*NTD + t2] = n; n++; }
                else g_rowpos[b*NTD + t2] = -1;
            }
        }
        g_nrows = n;
    }
}

// ---------------- permute LSTM weights: W2[k][blk*16 + jl*4 + q] ----------------
__global__ void permW_kernel(const float* __restrict__ We, const float* __restrict__ Wd)
{
    int idx = blockIdx.x * blockDim.x + threadIdx.x;
    int stride = gridDim.x * blockDim.x;
    for (int i = idx; i < 768*NG; i += stride) {
        int k = i >> 11, g2 = i & (NG - 1);
        int blk = g2 >> 4, x = g2 & 15, jl = x >> 2, q = x & 3;
        g_W2e[i] = We[(size_t)k*NG + q*NH + (blk << 2) + jl];
    }
    for (int i = idx; i < 1280*NG; i += stride) {
        int k = i >> 11, g2 = i & (NG - 1);
        int blk = g2 >> 4, x = g2 & 15, jl = x >> 2, q = x & 3;
        g_W2d[i] = Wd[(size_t)k*NG + q*NH + (blk << 2) + jl];
    }
}

__global__ void zero_kernel(float4* __restrict__ out, int n4)
{
    int idx = blockIdx.x * blockDim.x + threadIdx.x;
    int stride = gridDim.x * blockDim.x;
    float4 z = make_float4(0.f, 0.f, 0.f, 0.f);
    for (int i = idx; i < n4; i += stride) out[i] = z;
}

// ---------------- W_proj -> transposed bf16 hi/lo: Wt[v][k] ----------------
__global__ void wconv_kernel(const float* __restrict__ Wp)
{
    __shared__ float tile[64][65];
    int v0 = blockIdx.x * 64, k0 = blockIdx.y * 64;
    int tid = threadIdx.x;
    for (int i = tid; i < 4096; i += 256) {
        int kk = i >> 6, vv = i & 63;
        int v = v0 + vv;
        tile[kk][vv] = (v < NV) ? Wp[(size_t)(k0 + kk)*NV + v] : 0.f;
    }
    __syncthreads();
    for (int i = tid; i < 4096; i += 256) {
        int vv = i >> 6, kk = i & 63;
        float x = tile[kk][vv];
        __nv_bfloat16 hi = __float2bfloat16(x);
        float r = x - __bfloat162float(hi);
        size_t o = (size_t)(v0 + vv)*NH + k0 + kk;
        g_Wphi[o] = hi;
        g_Wplo[o] = __float2bfloat16(r);
    }
}

// ---------------- persistent encoder (weights in regs, pitch-18 smem) ----------------
__global__ void __launch_bounds__(256, 1)
enc_mega(const float* __restrict__ bias, const int* __restrict__ elen)
{
    extern __shared__ float sm[];
    float* xs = sm;                 // [768][PX]
    float* zp = sm + 768*PX;        // [256][PX]
    float* zz = zp + 256*PX;        // [256]

    int tid = threadIdx.x;
    int c = blockIdx.x;
    int gl = tid & 15, s = tid >> 4;
    int k0 = s * 48;

    float wreg[48];
    {
        const float* Wp = g_W2e + (c << 4) + gl;
        #pragma unroll
        for (int kk = 0; kk < 48; kk++) wreg[kk] = Wp[(size_t)(k0 + kk) * NG];
    }
    int g2r = tid >> 4;
    float bv = bias[(g2r & 3)*NH + (c << 2) + (g2r >> 2)];

    unsigned tgt = 0;
    for (int t = 0; t < NTE; t++) {
        const float* h_in  = g_h[t & 1];
        const float* c_in  = g_c[t & 1];
        float* h_out = g_h[(t + 1) & 1];
        float* c_out = g_c[(t + 1) & 1];

        #pragma unroll
        for (int b = 0; b < 16; b++)
            for (int k = tid; k < 768; k += 256) {
                float v = (k < NE) ? g_qemb[(b*NTE + t)*NE + k]
                                   : __ldcg(&h_in[b*NH + (k - NE)]);
                xs[k*PX + b] = v;
            }
        __syncthreads();

        u64 acc[8];
        #pragma unroll
        for (int p = 0; p < 8; p++) acc[p] = 0ULL;
        #pragma unroll
        for (int kk = 0; kk < 48; kk++) {
            u64 w2 = packdup(wreg[kk]);
            const u64* xk = (const u64*)(xs + (k0 + kk)*PX);
            #pragma unroll
            for (int p = 0; p < 8; p++) fma2(acc[p], xk[p], w2);
        }
        #pragma unroll
        for (int p = 0; p < 8; p++) {
            float lo, hi; unpack2(acc[p], lo, hi);
            zp[tid*PX + 2*p]   = lo;
            zp[tid*PX + 2*p+1] = hi;
        }
        __syncthreads();

        {
            int g2 = tid >> 4, b = tid & 15;
            float sum = 0.f;
            #pragma unroll
            for (int ss = 0; ss < 16; ss++) sum += zp[(g2 + 16*ss)*PX + b];
            zz[g2*16 + b] = sum + bv;
        }
        __syncthreads();

        if (tid < 64) {
            int jl = tid >> 4, b = tid & 15;
            int jg = (c << 2) + jl;
            float iv = zz[(jl*4 + 0)*16 + b];
            float jv = zz[(jl*4 + 1)*16 + b];
            float fv = zz[(jl*4 + 2)*16 + b];
            float ov = zz[(jl*4 + 3)*16 + b];
            float cold = c_in[b*NH + jg];
            float c2 = cold * sigf(fv + 1.f) + sigf(iv) * tanhf(jv);
            float h2 = tanhf(c2) * sigf(ov);
            bool valid = t < elen[b];
            float hold = xs[(NE + jg)*PX + b];
            h_out[b*NH + jg] = valid ? h2 : hold;
            c_out[b*NH + jg] = valid ? c2 : cold;
            g_encout[((size_t)b*NTE + t)*NH + jg] = valid ? h2 : 0.f;
        }
        tgt += 128;
        gbar(&g_barE, tgt);
    }
}

// ---------------- keys = enc_out @ W_mem ----------------
__global__ void keys_kernel(const float* __restrict__ Wm)
{
    extern __shared__ float sm[];
    const int KX = NH, KP = NH + 4;
    float* xs = sm;
    float* ws = sm + 16*KP;
    int tid = threadIdx.x;
    int cn = blockIdx.x;
    int cr = blockIdx.y;

    for (int i = tid; i < 16*KX; i += 256) {
        int rl = i >> 9, k = i & 511;
        xs[rl*KP + k] = g_encout[(cr*16 + rl)*NH + k];
    }
    for (int i = tid; i < 16*KX; i += 256) {
        int k = i >> 4, nl = i & 15;
        ws[nl*KP + k] = Wm[k*NH + cn*16 + nl];
    }
    __syncthreads();

    int nl = tid & 15, rl = tid >> 4;
    float a0 = 0.f, a1 = 0.f, a2 = 0.f, a3 = 0.f;
    const float* xp = xs + rl*KP;
    const float* wp = ws + nl*KP;
    #pragma unroll 8
    for (int k = 0; k < KX; k += 4) {
        float4 a = *(const float4*)(xp + k);
        float4 w = *(const float4*)(wp + k);
        a0 = fmaf(a.x, w.x, a0);
        a1 = fmaf(a.y, w.y, a1);
        a2 = fmaf(a.z, w.z, a2);
        a3 = fmaf(a.w, w.w, a3);
    }
    g_keys[(cr*16 + rl)*NH + cn*16 + nl] = (a0 + a1) + (a2 + a3);
}

// ---------------- persistent decoder ----------------
// Phase1 LSTM (weights in regs, pitch-18 staging). Phase2 pq (direct L2 reads).
// Phase3 scores/softmax/ctx (CTAs 0-15). Phase4 attn2 (direct L2 reads, writes bf16 A).
__global__ void __launch_bounds__(256, 1)
dec_mega(const float* __restrict__ bias, const float* __restrict__ Wq,
         const float* __restrict__ vatt, const float* __restrict__ Wa,
         const int* __restrict__ elen)
{
    extern __shared__ float sm[];
    float* xs  = sm;                    // [1280][PX]
    float* zp  = sm + 1280*PX;          // [256][PX]
    float* zz  = zp + 256*PX;           // [256]
    float* wqs = zz + 256;              // [512][4]
    float* was = wqs + 2048;            // [1024][4]
    float* pqv = sm;                    // phase3 aliases (inside xs)
    float* vsv = sm + 512;
    float* scv = sm + 1024;

    int tid = threadIdx.x;
    int c = blockIdx.x;
    int gl = tid & 15, s = tid >> 4;
    int k0 = s * 80;
    int n0 = c * 4;
    int bq = tid & 15, ks = tid >> 4;

    float wreg[80];
    {
        const float* Wp = g_W2d + (c << 4) + gl;
        #pragma unroll
        for (int kk = 0; kk < 80; kk++) wreg[kk] = Wp[(size_t)(k0 + kk) * NG];
    }
    for (int i = tid; i < 512*4; i += 256)
        wqs[i] = Wq[(size_t)(i >> 2)*NH + n0 + (i & 3)];
    for (int i = tid; i < 1024*4; i += 256)
        was[i] = Wa[(size_t)(i >> 2)*NH + n0 + (i & 3)];
    int g2r = tid >> 4;
    float bv = bias[(g2r & 3)*NH + (c << 2) + (g2r >> 2)];
    __syncthreads();

    unsigned tgt = 0;
    for (int t = 0; t < NTD; t++) {
        const float* h_in  = g_h[t & 1];
        const float* c_in  = g_c[t & 1];
        float* h_out = g_h[(t + 1) & 1];
        float* c_out = g_c[(t + 1) & 1];

        // ===== phase 1: LSTM =====
        #pragma unroll
        for (int b = 0; b < 16; b++)
            for (int k = tid; k < 1280; k += 256) {
                float v;
                if (k < NE)           v = g_remb[(b*NTD + t)*NE + k];
                else if (k < NE + NH) v = __ldcg(&g_attn[b*NH + (k - NE)]);
                else                  v = __ldcg(&h_in[b*NH + (k - NE - NH)]);
                xs[k*PX + b] = v;
            }
        __syncthreads();
        {
            u64 acc[8];
            #pragma unroll
            for (int p = 0; p < 8; p++) acc[p] = 0ULL;
            #pragma unroll
            for (int kk = 0; kk < 80; kk++) {
                u64 w2 = packdup(wreg[kk]);
                const u64* xk = (const u64*)(xs + (k0 + kk)*PX);
                #pragma unroll
                for (int p = 0; p < 8; p++) fma2(acc[p], xk[p], w2);
            }
            #pragma unroll
            for (int p = 0; p < 8; p++) {
                float lo, hi; unpack2(acc[p], lo, hi);
                zp[tid*PX + 2*p]   = lo;
                zp[tid*PX + 2*p+1] = hi;
            }
        }
        __syncthreads();
        {
            int g2 = tid >> 4, b = tid & 15;
            float sum = 0.f;
            #pragma unroll
            for (int ss = 0; ss < 16; ss++) sum += zp[(g2 + 16*ss)*PX + b];
            zz[g2*16 + b] = sum + bv;
        }
        __syncthreads();
        if (tid < 64) {
            int jl = tid >> 4, b = tid & 15;
            int jg = (c << 2) + jl;
            float iv = zz[(jl*4 + 0)*16 + b];
            float jv = zz[(jl*4 + 1)*16 + b];
            float fv = zz[(jl*4 + 2)*16 + b];
            float ov = zz[(jl*4 + 3)*16 + b];
            float cold = c_in[b*NH + jg];
            float c2 = cold * sigf(fv + 1.f) + sigf(iv) * tanhf(jv);
            float h2 = tanhf(c2) * sigf(ov);
            h_out[b*NH + jg] = h2;
            c_out[b*NH + jg] = c2;
        }
        tgt += 128; gbar(&g_barD, tgt);

        // ===== phase 2: pq = h2 @ Wq (4 n-cols per CTA, direct L2 reads) =====
        {
            const float4* wq4 = (const float4*)wqs;
            const float* hp = h_out + bq*NH + ks*32;
            float a0 = 0.f, a1 = 0.f, a2 = 0.f, a3 = 0.f;
            #pragma unroll
            for (int kk = 0; kk < 32; kk++) {
                float x = __ldcg(hp + kk);
                float4 w = wq4[ks*32 + kk];
                a0 = fmaf(x, w.x, a0);
                a1 = fmaf(x, w.y, a1);
                a2 = fmaf(x, w.z, a2);
                a3 = fmaf(x, w.w, a3);
            }
            zp[tid*PX + 0] = a0; zp[tid*PX + 1] = a1;
            zp[tid*PX + 2] = a2; zp[tid*PX + 3] = a3;
        }
        __syncthreads();
        if (tid < 64) {
            int bb = tid >> 2, j = tid & 3;
            float sv = 0.f;
            #pragma unroll
            for (int ss = 0; ss < 16; ss++) sv += zp[(bb + 16*ss)*PX + j];
            g_pq[bb*NH + n0 + j] = sv;
        }
        tgt += 128; gbar(&g_barD, tgt);

        // ===== phase 3: scores + softmax + ctx (CTAs 0..15) =====
        if (c < 16) {
            int b = c;
            for (int i = tid; i < NH; i += 256) { pqv[i] = __ldcg(&g_pq[b*NH + i]); vsv[i] = vatt[i]; }
            __syncthreads();
            int w = tid >> 5, l = tid & 31;
            int len = elen[b];
            for (int te = w; te < NTE; te += 8) {
                const float* kp = g_keys + ((size_t)b*NTE + te)*NH;
                float p = 0.f;
                for (int h = l; h < NH; h += 32)
                    p += vsv[h] * tanhf(kp[h] + pqv[h]);
                #pragma unroll
                for (int off = 16; off > 0; off >>= 1) p += __shfl_xor_sync(0xffffffffu, p, off);
                if (l == 0) scv[te] = (te < len) ? p : NEGV;
            }
            __syncthreads();
            if (tid < 32) {
                float a = scv[tid], b2 = scv[tid + 32];
                float m = fmaxf(a, b2);
                #pragma unroll
                for (int off = 16; off > 0; off >>= 1) m = fmaxf(m, __shfl_xor_sync(0xffffffffu, m, off));
                float e1 = expf(a - m), e2 = expf(b2 - m);
                float ssum = e1 + e2;
                #pragma unroll
                for (int off = 16; off > 0; off >>= 1) ssum += __shfl_xor_sync(0xffffffffu, ssum, off);
                float inv = 1.f / ssum;
                scv[tid] = e1 * inv; scv[tid + 32] = e2 * inv;
            }
            __syncthreads();
            for (int h = tid; h < NH; h += 256) {
                float acc = 0.f;
                const float* ep = g_encout + (size_t)b*NTE*NH + h;
                #pragma unroll 8
                for (int te = 0; te < NTE; te++)
                    acc = fmaf(scv[te], ep[(size_t)te*NH], acc);
                g_ctx[b*NH + h] = acc;
            }
        }
        tgt += 128; gbar(&g_barD, tgt);

        // ===== phase 4: attn2 = [h2|ctx] @ Wa (direct L2 reads), write attn + bf16 A =====
        {
            const float4* wa4 = (const float4*)was;
            const float* src = (ks < 8) ? (h_out + bq*NH + ks*64)
                                        : (g_ctx + bq*NH + (ks - 8)*64);
            float a0 = 0.f, a1 = 0.f, a2 = 0.f, a3 = 0.f;
            #pragma unroll
            for (int kk = 0; kk < 64; kk++) {
                float x = __ldcg(src + kk);
                float4 w = wa4[ks*64 + kk];
                a0 = fmaf(x, w.x, a0);
                a1 = fmaf(x, w.y, a1);
                a2 = fmaf(x, w.z, a2);
                a3 = fmaf(x, w.w, a3);
            }
            zp[tid*PX + 0] = a0; zp[tid*PX + 1] = a1;
            zp[tid*PX + 2] = a2; zp[tid*PX + 3] = a3;
        }
        __syncthreads();
        if (tid < 64) {
            int bb = tid >> 2, j = tid & 3;
            float sv = 0.f;
            #pragma unroll
            for (int ss = 0; ss < 16; ss++) sv += zp[(bb + 16*ss)*PX + j];
            g_attn[bb*NH + n0 + j] = sv;
            int m = g_rowpos[bb*NTD + t];
            if (m >= 0) {
                __nv_bfloat16 hi = __float2bfloat16(sv);
                g_Ahi[m*NH + n0 + j] = hi;
                g_Alo[m*NH + n0 + j] = __float2bfloat16(sv - __bfloat162float(hi));
            }
        }
        tgt += 128; gbar(&g_barD, tgt);
    }
}

// ---------------- HMMA projection (unchanged from round 6, proven) ----------------
#define PR_LDA 72
#define PROJ_SMEM (4*128*PR_LDA*2)

__device__ __forceinline__ void ldmA(uint32_t* a, uint32_t addr) {
    asm volatile("ldmatrix.sync.aligned.m8n8.x4.shared.b16 {%0,%1,%2,%3}, [%4];"
                 : "=r"(a[0]), "=r"(a[1]), "=r"(a[2]), "=r"(a[3]) : "r"(addr));
}
__device__ __forceinline__ void ldmB(uint32_t* b, uint32_t addr) {
    asm volatile("ldmatrix.sync.aligned.m8n8.x2.shared.b16 {%0,%1}, [%2];"
                 : "=r"(b[0]), "=r"(b[1]) : "r"(addr));
}
__device__ __forceinline__ void mma16816(float* c, const uint32_t* a, const uint32_t* b) {
    asm volatile("mma.sync.aligned.m16n8k16.row.col.f32.bf16.bf16.f32 "
                 "{%0,%1,%2,%3}, {%4,%5,%6,%7}, {%8,%9}, {%0,%1,%2,%3};"
                 : "+f"(c[0]), "+f"(c[1]), "+f"(c[2]), "+f"(c[3])
                 : "r"(a[0]), "r"(a[1]), "r"(a[2]), "r"(a[3]), "r"(b[0]), "r"(b[1]));
}

__global__ void __launch_bounds__(256, 1)
proj_hmma(float* __restrict__ out)
{
    extern __shared__ __nv_bfloat16 smb[];
    __nv_bfloat16* sAhi = smb;
    __nv_bfloat16* sAlo = smb + 128*PR_LDA;
    __nv_bfloat16* sBhi = smb + 2*128*PR_LDA;
    __nv_bfloat16* sBlo = smb + 3*128*PR_LDA;

    int m0 = blockIdx.x * 128;
    int n0 = blockIdx.y * 128;
    int nr = g_nrows;
    if (m0 >= nr) return;

    int tid = threadIdx.x;
    int wid = tid >> 5, lane = tid & 31;
    int m0w = (wid >> 2) * 64;
    int n0w = (wid & 3) * 32;

    uint32_t sb = smem_u32(smb);
    uint32_t aAhi = sb, aAlo = sb + 128*PR_LDA*2, aBhi = sb + 2*128*PR_LDA*2, aBlo = sb + 3*128*PR_LDA*2;

    float c[4][4][4];
    #pragma unroll
    for (int i = 0; i < 4; i++)
        #pragma unroll
        for (int j = 0; j < 4; j++)
            #pragma unroll
            for (int q = 0; q < 4; q++) c[i][j][q] = 0.f;

    for (int ch = 0; ch < 8; ch++) {
        int k0 = ch * 64;
        for (int i = tid; i < 1024; i += 256) {
            int m = i >> 3, kb = i & 7;
            size_t go = (size_t)(m0 + m)*NH + k0 + kb*8;
            int so = m*PR_LDA + kb*8;
            *(uint4*)&sAhi[so] = *(const uint4*)&g_Ahi[go];
            *(uint4*)&sAlo[so] = *(const uint4*)&g_Alo[go];
        }
        for (int i = tid; i < 1024; i += 256) {
            int n = i >> 3, kb = i & 7;
            size_t go = (size_t)(n0 + n)*NH + k0 + kb*8;
            int so = n*PR_LDA + kb*8;
            *(uint4*)&sBhi[so] = *(const uint4*)&g_Wphi[go];
            *(uint4*)&sBlo[so] = *(const uint4*)&g_Wplo[go];
        }
        __syncthreads();

        #pragma unroll
        for (int ksp = 0; ksp < 4; ksp++) {
            int kp = ksp * 16;
            uint32_t ahi[4][4], alo[4][4], bhi[4][2], blo[4][2];
            #pragma unroll
            for (int mt = 0; mt < 4; mt++) {
                uint32_t off = ((m0w + mt*16 + (lane & 15)) * PR_LDA + kp + ((lane >> 4) << 3)) * 2;
                ldmA(ahi[mt], aAhi + off);
                ldmA(alo[mt], aAlo + off);
            }
            #pragma unroll
            for (int nt = 0; nt < 4; nt++) {
                uint32_t off = ((n0w + nt*8 + (lane & 7)) * PR_LDA + kp + (((lane >> 3) & 1) << 3)) * 2;
                ldmB(bhi[nt], aBhi + off);
                ldmB(blo[nt], aBlo + off);
            }
            #pragma unroll
            for (int mt = 0; mt < 4; mt++)
                #pragma unroll
                for (int nt = 0; nt < 4; nt++) {
                    mma16816(c[mt][nt], ahi[mt], bhi[nt]);
                    mma16816(c[mt][nt], ahi[mt], blo[nt]);
                    mma16816(c[mt][nt], alo[mt], bhi[nt]);
                }
        }
        __syncthreads();
    }

    int rg = lane >> 2, cg = (lane & 3) * 2;
    #pragma unroll
    for (int mt = 0; mt < 4; mt++) {
        #pragma unroll
        for (int half = 0; half < 2; half++) {
            int mloc = m0w + mt*16 + rg + half*8;
            int m = m0 + mloc;
            if (m < nr) {
                int orow = g_outrow[m];
                float* obase = out + (size_t)orow*NV;
                #pragma unroll
                for (int nt = 0; nt < 4; nt++) {
                    int nn = n0 + n0w + nt*8 + cg;
                    float v0 = c[mt][nt][half*2 + 0];
                    float v1 = c[mt][nt][half*2 + 1];
                    if (nn + 1 < NV) {
                        *(float2*)(obase + nn) = make_float2(v0, v1);
                    } else if (nn < NV) {
                        obase[nn] = v0;
                    }
                }
            }
        }
    }
}

// ---------------- launch ----------------
extern "C" void kernel_launch(void* const* d_in, const int* in_sizes, int n_in,
                              void* d_out, int out_size)
{
    const int*   enc_in  = (const int*)d_in[0];
    const int*   dec_in  = (const int*)d_in[1];
    const int*   elen    = (const int*)d_in[2];
    const int*   dlen    = (const int*)d_in[3];
    const float* emb     = (const float*)d_in[4];
    const float* W_enc   = (const float*)d_in[5];
    const float* b_enc   = (const float*)d_in[6];
    const float* W_dec   = (const float*)d_in[7];
    const float* b_dec   = (const float*)d_in[8];
    const float* W_mem   = (const float*)d_in[9];
    const float* W_query = (const float*)d_in[10];
    const float* v_att   = (const float*)d_in[11];
    const float* W_attn  = (const float*)d_in[12];
    const float* W_proj  = (const float*)d_in[13];
    float* out = (float*)d_out;

    const int smemE = (768*PX + 256*PX + 256) * 4;                   //  74,752 B
    const int smemD = (1280*PX + 256*PX + 256 + 2048 + 4096) * 4;    // 136,192 B
    const int smemK = (2*16*(NH + 4)) * 4;                           //  66,048 B

    cudaFuncSetAttribute(enc_mega,    cudaFuncAttributeMaxDynamicSharedMemorySize, smemE);
    cudaFuncSetAttribute(dec_mega,    cudaFuncAttributeMaxDynamicSharedMemorySize, smemD);
    cudaFuncSetAttribute(keys_kernel, cudaFuncAttributeMaxDynamicSharedMemorySize, smemK);
    cudaFuncSetAttribute(proj_hmma,   cudaFuncAttributeMaxDynamicSharedMemorySize, PROJ_SMEM);

    prep_kernel<<<256, 256>>>(enc_in, dec_in, dlen, emb);
    permW_kernel<<<512, 256>>>(W_enc, W_dec);
    zero_kernel<<<1024, 256>>>((float4*)out, NB*NTD*NV/4);
    wconv_kernel<<<dim3(NVP/64, NH/64), 256>>>(W_proj);

    enc_mega<<<128, 256, smemE>>>(b_enc, elen);
    keys_kernel<<<dim3(32, 64), 256, smemK>>>(W_mem);
    dec_mega<<<128, 256, smemD>>>(b_dec, W_query, v_att, W_attn, elen);

    proj_hmma<<<dim3(4, 704), 256, PROJ_SMEM>>>(out);
}